// round 11
// baseline (speedup 1.0000x reference)
#include <cuda_runtime.h>
#include <cstdint>

// ===========================================================================
// JumpReLU SAE via mma.sync tf32. 8-warp CTAs, 64x64 warp tiles (crossbar-
// optimal fragment redundancy: A dup 4x, B dup 2x -> 182KB/iter vs 246KB).
//   prep:   W_encT = round_tf32(W_enc^T), W_decT = round_tf32(W_dec^T)
//           xR = round_tf32(x), bias_eff = b_enc - b_dec@W_enc (split-K)
//   GEMM1:  feats = round_tf32(JumpReLU(xR @ W_encT' + bias_eff)) -> d_out
//   GEMM2:  recon = feats @ W_decT' + b_dec
// ===========================================================================

#define BM 128
#define BN 256
#define BK 32
#define STAGES 4
#define NT 256            // 8 warps: 2 (M) x 4 (N), warp tile 64x64

#define ROWB 144                      // (BK+4)*4 B; 9x16B rows -> conflict-free ldmatrix
#define A_STAGE (BM * ROWB)           // 18432 B
#define B_STAGE (BN * ROWB)           // 36864 B
#define STAGE_BYTES (A_STAGE + B_STAGE)          // 55296 B
#define SMEM_TOTAL (STAGES * STAGE_BYTES)        // 221184 B

#define BC_SPLIT 8        // split-K factor for bias correction

// ------------------------- device scratch (no allocs allowed) --------------
__device__ __align__(16) float g_WencT[(size_t)16384 * 2048];   // [n][k] tf32
__device__ __align__(16) float g_WdecT[(size_t)2048 * 16384];   // [n][k] tf32
__device__ __align__(16) float g_xR[(size_t)8192 * 2048];       // x tf32
__device__ __align__(16) float g_biasPart[BC_SPLIT * 16384];
__device__ __align__(16) float g_biasEnc[16384];

// ------------------------------ PTX helpers --------------------------------
__device__ __forceinline__ uint32_t smem_u32(const void* p) {
    uint32_t a;
    asm("{ .reg .u64 t; cvta.to.shared.u64 t, %1; cvt.u32.u64 %0, t; }"
        : "=r"(a) : "l"(p));
    return a;
}
__device__ __forceinline__ void cp_async16(uint32_t dst, const void* src) {
    asm volatile("cp.async.cg.shared.global [%0], [%1], 16;"
                 :: "r"(dst), "l"(src) : "memory");
}
__device__ __forceinline__ void cp_commit() {
    asm volatile("cp.async.commit_group;" ::: "memory");
}
template <int N>
__device__ __forceinline__ void cp_wait_group() {
    asm volatile("cp.async.wait_group %0;" :: "n"(N) : "memory");
}
__device__ __forceinline__ void ldmatrix_x4(uint32_t* r, uint32_t addr) {
    asm volatile("ldmatrix.sync.aligned.m8n8.x4.shared.b16 {%0, %1, %2, %3}, [%4];"
                 : "=r"(r[0]), "=r"(r[1]), "=r"(r[2]), "=r"(r[3]) : "r"(addr));
}
__device__ __forceinline__ float round_tf32(float v) {
    float d;
    asm("cvt.rna.tf32.f32 %0, %1;" : "=f"(d) : "f"(v));
    return d;
}
__device__ __forceinline__ void mma_tf32(float* c, const uint32_t* a,
                                         const uint32_t* b) {
    asm volatile(
        "mma.sync.aligned.m16n8k8.row.col.f32.tf32.tf32.f32 "
        "{%0, %1, %2, %3}, {%4, %5, %6, %7}, {%8, %9}, {%0, %1, %2, %3};"
        : "+f"(c[0]), "+f"(c[1]), "+f"(c[2]), "+f"(c[3])
        : "r"(a[0]), "r"(a[1]), "r"(a[2]), "r"(a[3]), "r"(b[0]), "r"(b[1]));
}

// ------------------------------- prep kernels ------------------------------
// dst[C][R] = round_tf32(src[R][C])
__global__ void transpose_round_kernel(const float* __restrict__ src,
                                       float* __restrict__ dst, int R, int C) {
    __shared__ float tile[32][33];
    int x = blockIdx.x * 32 + threadIdx.x;
    int y = blockIdx.y * 32 + threadIdx.y;
    #pragma unroll
    for (int j = 0; j < 32; j += 8)
        tile[threadIdx.y + j][threadIdx.x] =
            round_tf32(src[(size_t)(y + j) * C + x]);
    __syncthreads();
    x = blockIdx.y * 32 + threadIdx.x;
    y = blockIdx.x * 32 + threadIdx.y;
    #pragma unroll
    for (int j = 0; j < 32; j += 8)
        dst[(size_t)(y + j) * R + x] = tile[threadIdx.x][threadIdx.y + j];
}

__global__ void round_kernel(const float* __restrict__ src,
                             float* __restrict__ dst, size_t n4) {
    size_t i = (size_t)blockIdx.x * blockDim.x + threadIdx.x;
    if (i < n4) {
        float4 v = reinterpret_cast<const float4*>(src)[i];
        v.x = round_tf32(v.x); v.y = round_tf32(v.y);
        v.z = round_tf32(v.z); v.w = round_tf32(v.w);
        reinterpret_cast<float4*>(dst)[i] = v;
    }
}

// split-K partials: part[ky][n] = sum_{k in chunk ky} b_dec[k] * W_enc[k][n]
__global__ void bias_part_kernel(const float* __restrict__ W_enc,
                                 const float* __restrict__ b_dec,
                                 float* __restrict__ part, int K, int N) {
    const int n  = blockIdx.x * blockDim.x + threadIdx.x;
    const int ky = blockIdx.y;
    const int kc = K / BC_SPLIT;
    const int k0 = ky * kc;
    float s = 0.f;
    #pragma unroll 4
    for (int k = k0; k < k0 + kc; k++)
        s += b_dec[k] * W_enc[(size_t)k * N + n];
    part[(size_t)ky * N + n] = s;
}

// bias_eff[n] = b_enc[n] - sum_ky part[ky][n]   (deterministic reduce)
__global__ void bias_reduce_kernel(const float* __restrict__ part,
                                   const float* __restrict__ b_enc,
                                   float* __restrict__ out, int N) {
    const int n = blockIdx.x * blockDim.x + threadIdx.x;
    float s = 0.f;
    #pragma unroll
    for (int ky = 0; ky < BC_SPLIT; ky++)
        s += part[(size_t)ky * N + n];
    out[n] = b_enc[n] - s;
}

// ------------------------------- main GEMM ---------------------------------
// ENC: JumpReLU epilogue, output stored tf32-rounded (consumed by decode)
template <bool ENC>
__global__ __launch_bounds__(NT, 1)
void sae_gemm(const float* __restrict__ A,      // [M][K] K-contig, tf32 values
              const float* __restrict__ B,      // [Ntot][K] K-contig, tf32 values
              const float* __restrict__ bias,   // [Ntot]
              const float* __restrict__ thr,    // [Ntot] (ENC only)
              float* __restrict__ C,            // [M][Ntot]
              int K, int Nout) {
    extern __shared__ __align__(16) char smem[];
    const uint32_t sb = smem_u32(smem);

    const int tid = threadIdx.x;
    const int wid = tid >> 5;
    const int l   = tid & 31;
    const int wm  = wid & 1;        // 0..1 (M)
    const int wn  = wid >> 1;       // 0..3 (N)

    const float* Ag = A + (size_t)blockIdx.y * BM * K;
    const float* Bg = B + (size_t)blockIdx.x * BN * K;

    const int n_iters = K / BK;

    // cp.async mapping: 16B chunks, 256 threads.
    const int ldRow = tid >> 3;          // 0..31
    const int ldChk = tid & 7;           // 0..7
    const size_t ldSrc  = (size_t)ldRow * K + ldChk * 4;
    const uint32_t ldDst = (uint32_t)(ldRow * ROWB + ldChk * 16);

    auto issue_tile = [&](int t) {
        if (t < n_iters) {
            const uint32_t st = sb + (t & (STAGES - 1)) * STAGE_BYTES;
            const int k0 = t * BK;
            const float* aS = Ag + k0;
            const float* bS = Bg + k0;
            #pragma unroll
            for (int i = 0; i < 4; i++)      // A: 128 rows
                cp_async16(st + ldDst + i * 32 * ROWB,
                           aS + ldSrc + (size_t)i * 32 * K);
            #pragma unroll
            for (int i = 0; i < 8; i++)      // B: 256 rows
                cp_async16(st + A_STAGE + ldDst + i * 32 * ROWB,
                           bS + ldSrc + (size_t)i * 32 * K);
        }
        cp_commit();   // uniform one group per slot (possibly empty)
    };

    // fragment smem byte-offsets (relative to stage base)
    uint32_t aoff[4], boff[4];
    #pragma unroll
    for (int i = 0; i < 4; i++)
        aoff[i] = (uint32_t)((wm * 64 + i * 16 + (l & 15)) * ROWB
                             + (l >> 4) * 16);
    #pragma unroll
    for (int j = 0; j < 4; j++)
        boff[j] = (uint32_t)(A_STAGE
                             + (wn * 64 + j * 16 + (l & 7) + ((l >> 4) << 3)) * ROWB
                             + ((l >> 3) & 1) * 16);

    float acc[4][8][4];
    #pragma unroll
    for (int i = 0; i < 4; i++)
        #pragma unroll
        for (int j = 0; j < 8; j++)
            #pragma unroll
            for (int q = 0; q < 4; q++) acc[i][j][q] = 0.f;

    issue_tile(0);
    issue_tile(1);
    issue_tile(2);

    for (int it = 0; it < n_iters; ++it) {
        cp_wait_group<2>();          // tile `it` resident
        __syncthreads();             // all warps done with iter it-1
        issue_tile(it + 3);          // writes slot (it-1)%4: safe after barrier

        const uint32_t st = sb + (it & (STAGES - 1)) * STAGE_BYTES;
        #pragma unroll
        for (int ks = 0; ks < BK / 8; ks++) {
            uint32_t af[4][4], bf[4][4];
            #pragma unroll
            for (int i = 0; i < 4; i++)
                ldmatrix_x4(af[i], st + aoff[i] + ks * 32);
            #pragma unroll
            for (int j = 0; j < 4; j++)
                ldmatrix_x4(bf[j], st + boff[j] + ks * 32);
            #pragma unroll
            for (int i = 0; i < 4; i++)
                #pragma unroll
                for (int j = 0; j < 4; j++) {
                    mma_tf32(acc[i][2 * j],     af[i], &bf[j][0]);
                    mma_tf32(acc[i][2 * j + 1], af[i], &bf[j][2]);
                }
        }
    }

    // ---- fused epilogue ----
    const int cRow = blockIdx.y * BM + wm * 64;
    const int cCol = blockIdx.x * BN + wn * 64;

    #pragma unroll
    for (int i = 0; i < 4; i++) {
        const int r0 = cRow + i * 16 + (l >> 2);
        #pragma unroll
        for (int j = 0; j < 8; j++) {
            const int col = cCol + j * 8 + (l & 3) * 2;
            const float2 bv = *reinterpret_cast<const float2*>(bias + col);
            float v0 = acc[i][j][0] + bv.x;
            float v1 = acc[i][j][1] + bv.y;
            float v2 = acc[i][j][2] + bv.x;
            float v3 = acc[i][j][3] + bv.y;
            if (ENC) {
                const float2 tv = *reinterpret_cast<const float2*>(thr + col);
                v0 = (v0 > tv.x) ? round_tf32(v0) : 0.f;
                v1 = (v1 > tv.y) ? round_tf32(v1) : 0.f;
                v2 = (v2 > tv.x) ? round_tf32(v2) : 0.f;
                v3 = (v3 > tv.y) ? round_tf32(v3) : 0.f;
            }
            const size_t o0 = (size_t)r0 * Nout + col;
            const size_t o1 = (size_t)(r0 + 8) * Nout + col;
            *reinterpret_cast<float2*>(C + o0) = make_float2(v0, v1);
            *reinterpret_cast<float2*>(C + o1) = make_float2(v2, v3);
        }
    }
}

// ------------------------------- launcher ----------------------------------
extern "C" void kernel_launch(void* const* d_in, const int* in_sizes, int n_in,
                              void* d_out, int out_size) {
    const float* x     = (const float*)d_in[0];   // [8192, 2048]
    const float* W_enc = (const float*)d_in[1];   // [2048, 16384]
    const float* b_enc = (const float*)d_in[2];   // [16384]
    const float* thr   = (const float*)d_in[3];   // [16384]
    const float* W_dec = (const float*)d_in[4];   // [16384, 2048]
    const float* b_dec = (const float*)d_in[5];   // [2048]

    const int Nrows = 8192, D = 2048, S = 16384;

    float* recon = (float*)d_out;                       // [8192, 2048]
    float* feats = (float*)d_out + (size_t)Nrows * D;   // [8192, 16384]

    float *wEncT, *wDecT, *xR, *biasPart, *biasEnc;
    cudaGetSymbolAddress((void**)&wEncT, g_WencT);
    cudaGetSymbolAddress((void**)&wDecT, g_WdecT);
    cudaGetSymbolAddress((void**)&xR, g_xR);
    cudaGetSymbolAddress((void**)&biasPart, g_biasPart);
    cudaGetSymbolAddress((void**)&biasEnc, g_biasEnc);

    cudaFuncSetAttribute(sae_gemm<true>,
                         cudaFuncAttributeMaxDynamicSharedMemorySize, SMEM_TOTAL);
    cudaFuncSetAttribute(sae_gemm<false>,
                         cudaFuncAttributeMaxDynamicSharedMemorySize, SMEM_TOTAL);

    // prep: tf32-rounded transposed weights, rounded x, effective encoder bias
    transpose_round_kernel<<<dim3(S / 32, D / 32), dim3(32, 8)>>>(W_enc, wEncT, D, S);
    transpose_round_kernel<<<dim3(D / 32, S / 32), dim3(32, 8)>>>(W_dec, wDecT, S, D);
    {
        size_t n4 = (size_t)Nrows * D / 4;
        round_kernel<<<(unsigned)((n4 + 255) / 256), 256>>>(x, xR, n4);
    }
    bias_part_kernel<<<dim3(S / 256, BC_SPLIT), 256>>>(W_enc, b_dec, biasPart, D, S);
    bias_reduce_kernel<<<S / 256, 256>>>(biasPart, b_enc, biasEnc, S);

    // encode: feats = round_tf32(JumpReLU(xR @ W_enc + bias_eff)) -> d_out
    sae_gemm<true><<<dim3(S / BN, Nrows / BM), NT, SMEM_TOTAL>>>(
        xR, wEncT, biasEnc, thr, feats, D, S);

    // decode: recon = feats @ W_dec + b_dec   (feats already tf32 values)
    sae_gemm<false><<<dim3(D / BN, Nrows / BM), NT, SMEM_TOTAL>>>(
        feats, wDecT, b_dec, nullptr, recon, S, D);
}